// round 13
// baseline (speedup 1.0000x reference)
#include <cuda_runtime.h>
#include <cuda_fp16.h>
#include <cuda_bf16.h>

#define N_NODES 100000
#define N_EDGES 3200000
#define F_IN 8
#define F_HID 64

// Scratch: __device__ globals (GPU DRAM; allocation-free rule)
__device__ float g_deg[N_NODES];                           // accumulated WITHOUT self-loop
__device__ float g_dinv[N_NODES];
__device__ __align__(16) unsigned g_xsh[N_NODES * 4];      // dinv[i]*x[i] as 8 fp16 (4x half2)
__device__ __align__(16) unsigned g_acc1h[N_NODES * 4];    // 8 fp16 accumulators/node (4x half2)
__device__ float g_sd[N_NODES];                            // dinv[i] * s[i]
__device__ float g_acc2[N_NODES];                          // layer-2 accumulator

__device__ __forceinline__ unsigned h2_bits(__half2 h) {
    union { __half2 h; unsigned u; } cvt; cvt.h = h; return cvt.u;
}
__device__ __forceinline__ __half2 bits_h2(unsigned u) {
    union { unsigned u; __half2 h; } cvt; cvt.u = u; return cvt.h;
}

// packed f32x2 helpers (Blackwell dual-issue FMA: FFMA2 only via PTX fma.rn.f32x2)
#define PACK_F32X2(out, lo, hi) \
    asm("mov.b64 %0, {%1, %2};" : "=l"(out) : "f"(lo), "f"(hi))
#define UNPACK_F32X2(lo, hi, in) \
    asm("mov.b64 {%0, %1}, %2;" : "=f"(lo), "=f"(hi) : "l"(in))
#define FMA_F32X2(d, a, b, c) \
    asm("fma.rn.f32x2 %0, %1, %2, %3;" : "=l"(d) : "l"(a), "l"(b), "l"(c))

// ---------------------------------------------------------------------------
// 1) deg accumulate: deg[col] += w   (deg zeroed by memset; self-loop +1 in dinv)
__global__ void k_deg_acc(const int* __restrict__ ei, const float* __restrict__ w) {
    int e = blockIdx.x * blockDim.x + threadIdx.x;
    if (e >= N_EDGES) return;
    atomicAdd(&g_deg[ei[N_EDGES + e]], w[e]);
}

// 2) dinv = rsqrt(1 + deg); xsh = fp16(dinv*x); zero acc1h & acc2 (fused init)
__global__ void k_dinv_xs(const float* __restrict__ x) {
    int i = blockIdx.x * blockDim.x + threadIdx.x;
    if (i >= N_NODES) return;
    float dv = rsqrtf(1.0f + g_deg[i]);     // +1 = self-loop weight
    g_dinv[i] = dv;
    const float4* xr = (const float4*)(x + (size_t)i * F_IN);
    float4 a = xr[0], b = xr[1];
    uint4 pk;
    pk.x = h2_bits(__floats2half2_rn(a.x * dv, a.y * dv));
    pk.y = h2_bits(__floats2half2_rn(a.z * dv, a.w * dv));
    pk.z = h2_bits(__floats2half2_rn(b.x * dv, b.y * dv));
    pk.w = h2_bits(__floats2half2_rn(b.z * dv, b.w * dv));
    ((uint4*)g_xsh)[i] = pk;
    ((uint4*)g_acc1h)[i] = make_uint4(0u, 0u, 0u, 0u);
    g_acc2[i] = 0.0f;
}

// fire-and-forget packed-half reduction: 8 halves in one 16B RED (sm_103a)
__device__ __forceinline__ void red_add_v4_f16x2(unsigned* p, unsigned h0, unsigned h1,
                                                 unsigned h2, unsigned h3) {
    asm volatile("red.global.add.noftz.v4.f16x2 [%0], {%1,%2,%3,%4};"
                 :: "l"(p), "r"(h0), "r"(h1), "r"(h2), "r"(h3) : "memory");
}

// 3) layer-1 edge pass, 1 edge/thread: acc1[c] += w * xs[r]
//    1 LDG.128 gather (fp16 xs) + 1 RED.128; multiply in fp32 for precision.
__global__ void k_layer1_edges(const int* __restrict__ ei, const float* __restrict__ w) {
    int e = blockIdx.x * blockDim.x + threadIdx.x;
    if (e >= N_EDGES) return;
    int r = ei[e];
    int c = ei[N_EDGES + e];
    float we = w[e];
    uint4 u = __ldg((const uint4*)(g_xsh + (size_t)r * 4));
    float2 p0 = __half22float2(bits_h2(u.x));
    float2 p1 = __half22float2(bits_h2(u.y));
    float2 p2 = __half22float2(bits_h2(u.z));
    float2 p3 = __half22float2(bits_h2(u.w));
    unsigned h0 = h2_bits(__floats2half2_rn(we * p0.x, we * p0.y));
    unsigned h1 = h2_bits(__floats2half2_rn(we * p1.x, we * p1.y));
    unsigned h2 = h2_bits(__floats2half2_rn(we * p2.x, we * p2.y));
    unsigned h3 = h2_bits(__floats2half2_rn(we * p3.x, we * p3.y));
    red_add_v4_f16x2(g_acc1h + (size_t)c * 4, h0, h1, h2, h3);
}

// 4) node MLP, cooperative 2-thread/node split:
//    each pair-thread loads half the prologue, exchanges via shfl, does 32 of 64 f's.
__global__ void k_node_mlp(const float* __restrict__ x,
                           const float* __restrict__ W1,
                           const float* __restrict__ b1,
                           const float* __restrict__ W2) {
    __shared__ unsigned long long sW1p[F_IN * F_HID / 2];  // [k][fp]: packed (W1[k][2fp], W1[k][2fp+1])
    __shared__ float2 sb1p[F_HID / 2];
    __shared__ float  sW2[F_HID];
    for (int t = threadIdx.x; t < F_IN * F_HID / 2; t += blockDim.x) {
        float2 v = ((const float2*)W1)[t];   // W1 row-major [8][64]: adjacent f contiguous
        union { float2 f; unsigned long long u; } cvt; cvt.f = v;
        sW1p[t] = cvt.u;
    }
    for (int t = threadIdx.x; t < F_HID / 2; t += blockDim.x) sb1p[t] = ((const float2*)b1)[t];
    for (int t = threadIdx.x; t < F_HID; t += blockDim.x) sW2[t] = W2[t];
    __syncthreads();

    int gid = blockIdx.x * blockDim.x + threadIdx.x;
    int i = gid >> 1;
    int half_id = gid & 1;
    if (i >= N_NODES) return;

    float dv = g_dinv[i];
    float dv2 = dv * dv;

    // each pair-thread loads its half: 4 fp16 accs (8B) + 4 fp32 x (16B)
    uint2 u = __ldg((const uint2*)(g_acc1h + (size_t)i * 4 + half_id * 2));
    float2 f0 = __half22float2(bits_h2(u.x));
    float2 f1 = __half22float2(bits_h2(u.y));
    float4 X = __ldg((const float4*)(x + (size_t)i * F_IN + half_id * 4));

    float own0 = dv * f0.x + dv2 * X.x;
    float own1 = dv * f0.y + dv2 * X.y;
    float own2 = dv * f1.x + dv2 * X.z;
    float own3 = dv * f1.y + dv2 * X.w;

    // exchange halves with the partner thread (two 64-bit shuffles)
    unsigned long long pk01, pk23;
    PACK_F32X2(pk01, own0, own1);
    PACK_F32X2(pk23, own2, own3);
    unsigned long long ot01 = __shfl_xor_sync(0xffffffffu, pk01, 1);
    unsigned long long ot23 = __shfl_xor_sync(0xffffffffu, pk23, 1);
    float o0, o1, o2, o3;
    UNPACK_F32X2(o0, o1, ot01);
    UNPACK_F32X2(o2, o3, ot23);

    float a[F_IN];
    if (half_id == 0) {
        a[0]=own0; a[1]=own1; a[2]=own2; a[3]=own3; a[4]=o0; a[5]=o1; a[6]=o2; a[7]=o3;
    } else {
        a[0]=o0; a[1]=o1; a[2]=o2; a[3]=o3; a[4]=own0; a[5]=own1; a[6]=own2; a[7]=own3;
    }

    // broadcast-pack each a[k] into both halves once
    unsigned long long apk[F_IN];
    #pragma unroll
    for (int k = 0; k < F_IN; k++) PACK_F32X2(apk[k], a[k], a[k]);

    float s = 0.0f;
    int fp0 = half_id * (F_HID / 4);     // 16 fp-pairs (=32 f's) per thread
    #pragma unroll 4
    for (int q = 0; q < F_HID / 4; q++) {
        int fp = fp0 + q;
        float2 bb = sb1p[fp];
        unsigned long long acc;
        PACK_F32X2(acc, bb.x, bb.y);
        #pragma unroll
        for (int k = 0; k < F_IN; k++)
            FMA_F32X2(acc, apk[k], sW1p[k * (F_HID / 2) + fp], acc);
        float lo, hi;
        UNPACK_F32X2(lo, hi, acc);
        s = fmaf(fmaxf(lo, 0.0f), sW2[2 * fp],     s);
        s = fmaf(fmaxf(hi, 0.0f), sW2[2 * fp + 1], s);
    }
    s += __shfl_xor_sync(0xffffffffu, s, 1);
    if (half_id == 0) g_sd[i] = dv * s;
}

// 5) layer-2 edge pass, 1 edge/thread: acc2[c] += w * sd[r]
__global__ void k_layer2_edges(const int* __restrict__ ei, const float* __restrict__ w) {
    int e = blockIdx.x * blockDim.x + threadIdx.x;
    if (e >= N_EDGES) return;
    int r = ei[e];
    int c = ei[N_EDGES + e];
    atomicAdd(&g_acc2[c], w[e] * __ldg(&g_sd[r]));
}

// 6) epilogue: out = b2 + dinv * (acc2 + sd)   (plain stores to d_out)
__global__ void k_out(const float* __restrict__ b2, float* __restrict__ out) {
    int i = blockIdx.x * blockDim.x + threadIdx.x;
    if (i < N_NODES) out[i] = b2[0] + g_dinv[i] * (g_acc2[i] + g_sd[i]);
}

extern "C" void kernel_launch(void* const* d_in, const int* in_sizes, int n_in,
                              void* d_out, int out_size) {
    const float* x  = (const float*)d_in[0];
    const int*   ei = (const int*)d_in[1];     // int32 (JAX x64 disabled)
    const float* w  = (const float*)d_in[2];
    const float* W1 = (const float*)d_in[3];
    const float* b1 = (const float*)d_in[4];
    const float* W2 = (const float*)d_in[5];
    const float* b2 = (const float*)d_in[6];
    float* out = (float*)d_out;

    // zero deg via memset graph node (self-loop +1 folded into k_dinv_xs)
    void* deg_ptr = nullptr;
    cudaGetSymbolAddress(&deg_ptr, g_deg);
    cudaMemsetAsync(deg_ptr, 0, N_NODES * sizeof(float));

    const int TB = 256;
    const int gridN  = (N_NODES + TB - 1) / TB;
    const int gridN2 = (2 * N_NODES + TB - 1) / TB;
    const int gridE  = (N_EDGES + TB - 1) / TB;

    k_deg_acc<<<gridE, TB>>>(ei, w);
    k_dinv_xs<<<gridN, TB>>>(x);
    k_layer1_edges<<<gridE, TB>>>(ei, w);
    k_node_mlp<<<gridN2, TB>>>(x, W1, b1, W2);
    k_layer2_edges<<<gridE, TB>>>(ei, w);
    k_out<<<gridN, TB>>>(b2, out);
}

// round 14
// speedup vs baseline: 1.0884x; 1.0884x over previous
#include <cuda_runtime.h>
#include <cuda_fp16.h>
#include <cuda_bf16.h>

#define N_NODES 100000
#define N_EDGES 3200000
#define F_IN 8
#define F_HID 64

// Scratch: __device__ globals (GPU DRAM; allocation-free rule)
__device__ float g_deg[N_NODES];                           // accumulated WITHOUT self-loop
__device__ float g_dinv[N_NODES];
__device__ __align__(16) unsigned g_xsh[N_NODES * 4];      // dinv[i]*x[i] as 8 fp16 (4x half2)
__device__ __align__(16) unsigned g_acc1h[N_NODES * 4];    // 8 fp16 accumulators/node (4x half2)
__device__ float g_sd[N_NODES];                            // dinv[i] * s[i]
__device__ float g_acc2[N_NODES];                          // layer-2 accumulator

// MLP params in constant memory (uniform LDC path; filled per-call via D2D memcpy)
__constant__ float c_W1[F_IN * F_HID];   // row-major [8][64]; pair layout == raw bytes
__constant__ float c_b1[F_HID];
__constant__ float c_W2[F_HID];

__device__ __forceinline__ unsigned h2_bits(__half2 h) {
    union { __half2 h; unsigned u; } cvt; cvt.h = h; return cvt.u;
}
__device__ __forceinline__ __half2 bits_h2(unsigned u) {
    union { unsigned u; __half2 h; } cvt; cvt.u = u; return cvt.h;
}

// packed f32x2 helpers (Blackwell dual-issue FMA: FFMA2 only via PTX fma.rn.f32x2)
#define PACK_F32X2(out, lo, hi) \
    asm("mov.b64 %0, {%1, %2};" : "=l"(out) : "f"(lo), "f"(hi))
#define UNPACK_F32X2(lo, hi, in) \
    asm("mov.b64 {%0, %1}, %2;" : "=f"(lo), "=f"(hi) : "l"(in))
#define FMA_F32X2(d, a, b, c) \
    asm("fma.rn.f32x2 %0, %1, %2, %3;" : "=l"(d) : "l"(a), "l"(b), "l"(c))

// ---------------------------------------------------------------------------
// 1) deg accumulate: deg[col] += w   (deg zeroed by memset; self-loop +1 in dinv)
__global__ void k_deg_acc(const int* __restrict__ ei, const float* __restrict__ w) {
    int e = blockIdx.x * blockDim.x + threadIdx.x;
    if (e >= N_EDGES) return;
    atomicAdd(&g_deg[ei[N_EDGES + e]], w[e]);
}

// 2) dinv = rsqrt(1 + deg); xsh = fp16(dinv*x); zero acc1h & acc2 (fused init)
__global__ void k_dinv_xs(const float* __restrict__ x) {
    int i = blockIdx.x * blockDim.x + threadIdx.x;
    if (i >= N_NODES) return;
    float dv = rsqrtf(1.0f + g_deg[i]);     // +1 = self-loop weight
    g_dinv[i] = dv;
    const float4* xr = (const float4*)(x + (size_t)i * F_IN);
    float4 a = xr[0], b = xr[1];
    uint4 pk;
    pk.x = h2_bits(__floats2half2_rn(a.x * dv, a.y * dv));
    pk.y = h2_bits(__floats2half2_rn(a.z * dv, a.w * dv));
    pk.z = h2_bits(__floats2half2_rn(b.x * dv, b.y * dv));
    pk.w = h2_bits(__floats2half2_rn(b.z * dv, b.w * dv));
    ((uint4*)g_xsh)[i] = pk;
    ((uint4*)g_acc1h)[i] = make_uint4(0u, 0u, 0u, 0u);
    g_acc2[i] = 0.0f;
}

// fire-and-forget packed-half reduction: 8 halves in one 16B RED (sm_103a)
__device__ __forceinline__ void red_add_v4_f16x2(unsigned* p, unsigned h0, unsigned h1,
                                                 unsigned h2, unsigned h3) {
    asm volatile("red.global.add.noftz.v4.f16x2 [%0], {%1,%2,%3,%4};"
                 :: "l"(p), "r"(h0), "r"(h1), "r"(h2), "r"(h3) : "memory");
}

// 3) layer-1 edge pass, 1 edge/thread: acc1[c] += w * xs[r]
//    1 LDG.128 gather (fp16 xs) + 1 RED.128; multiply in fp32 for precision.
__global__ void k_layer1_edges(const int* __restrict__ ei, const float* __restrict__ w) {
    int e = blockIdx.x * blockDim.x + threadIdx.x;
    if (e >= N_EDGES) return;
    int r = ei[e];
    int c = ei[N_EDGES + e];
    float we = w[e];
    uint4 u = __ldg((const uint4*)(g_xsh + (size_t)r * 4));
    float2 p0 = __half22float2(bits_h2(u.x));
    float2 p1 = __half22float2(bits_h2(u.y));
    float2 p2 = __half22float2(bits_h2(u.z));
    float2 p3 = __half22float2(bits_h2(u.w));
    unsigned h0 = h2_bits(__floats2half2_rn(we * p0.x, we * p0.y));
    unsigned h1 = h2_bits(__floats2half2_rn(we * p1.x, we * p1.y));
    unsigned h2 = h2_bits(__floats2half2_rn(we * p2.x, we * p2.y));
    unsigned h3 = h2_bits(__floats2half2_rn(we * p3.x, we * p3.y));
    red_add_v4_f16x2(g_acc1h + (size_t)c * 4, h0, h1, h2, h3);
}

// 4) node MLP, 1 thread/node, f-pairs via fma.rn.f32x2, params in __constant__:
//    a = dinv*acc1 + dinv^2*x ; s = relu(a@W1+b1)@W2 ; sd = dinv*s
__global__ void k_node_mlp(const float* __restrict__ x) {
    int i = blockIdx.x * blockDim.x + threadIdx.x;
    if (i >= N_NODES) return;

    float dv = g_dinv[i];
    float dv2 = dv * dv;
    uint4 u = __ldg((const uint4*)(g_acc1h + (size_t)i * 4));
    float2 f0 = __half22float2(bits_h2(u.x));
    float2 f1 = __half22float2(bits_h2(u.y));
    float2 f2 = __half22float2(bits_h2(u.z));
    float2 f3 = __half22float2(bits_h2(u.w));
    const float4* xr = (const float4*)(x + (size_t)i * F_IN);
    float4 X0 = __ldg(xr), X1 = __ldg(xr + 1);
    float a[F_IN];
    a[0] = dv * f0.x + dv2 * X0.x;  a[1] = dv * f0.y + dv2 * X0.y;
    a[2] = dv * f1.x + dv2 * X0.z;  a[3] = dv * f1.y + dv2 * X0.w;
    a[4] = dv * f2.x + dv2 * X1.x;  a[5] = dv * f2.y + dv2 * X1.y;
    a[6] = dv * f3.x + dv2 * X1.z;  a[7] = dv * f3.y + dv2 * X1.w;

    // broadcast-pack each a[k] into both halves once
    unsigned long long apk[F_IN];
    #pragma unroll
    for (int k = 0; k < F_IN; k++) PACK_F32X2(apk[k], a[k], a[k]);

    const unsigned long long* W1p = (const unsigned long long*)c_W1;  // [k][fp] pairs
    const float2* b1p = (const float2*)c_b1;

    float s = 0.0f;
    #pragma unroll
    for (int fp = 0; fp < F_HID / 2; fp++) {
        float2 bb = b1p[fp];
        unsigned long long acc;
        PACK_F32X2(acc, bb.x, bb.y);
        #pragma unroll
        for (int k = 0; k < F_IN; k++)
            FMA_F32X2(acc, apk[k], W1p[k * (F_HID / 2) + fp], acc);
        float lo, hi;
        UNPACK_F32X2(lo, hi, acc);
        s = fmaf(fmaxf(lo, 0.0f), c_W2[2 * fp],     s);
        s = fmaf(fmaxf(hi, 0.0f), c_W2[2 * fp + 1], s);
    }
    g_sd[i] = dv * s;
}

// 5) layer-2 edge pass, 1 edge/thread: acc2[c] += w * sd[r]
__global__ void k_layer2_edges(const int* __restrict__ ei, const float* __restrict__ w) {
    int e = blockIdx.x * blockDim.x + threadIdx.x;
    if (e >= N_EDGES) return;
    int r = ei[e];
    int c = ei[N_EDGES + e];
    atomicAdd(&g_acc2[c], w[e] * __ldg(&g_sd[r]));
}

// 6) epilogue: out = b2 + dinv * (acc2 + sd)   (plain stores to d_out)
__global__ void k_out(const float* __restrict__ b2, float* __restrict__ out) {
    int i = blockIdx.x * blockDim.x + threadIdx.x;
    if (i < N_NODES) out[i] = b2[0] + g_dinv[i] * (g_acc2[i] + g_sd[i]);
}

extern "C" void kernel_launch(void* const* d_in, const int* in_sizes, int n_in,
                              void* d_out, int out_size) {
    const float* x  = (const float*)d_in[0];
    const int*   ei = (const int*)d_in[1];     // int32 (JAX x64 disabled)
    const float* w  = (const float*)d_in[2];
    const float* W1 = (const float*)d_in[3];
    const float* b1 = (const float*)d_in[4];
    const float* W2 = (const float*)d_in[5];
    const float* b2 = (const float*)d_in[6];
    float* out = (float*)d_out;

    // zero deg via memset node; stage MLP params into __constant__ (D2D, capturable)
    void* deg_ptr = nullptr;
    cudaGetSymbolAddress(&deg_ptr, g_deg);
    cudaMemsetAsync(deg_ptr, 0, N_NODES * sizeof(float));
    cudaMemcpyToSymbolAsync(c_W1, W1, F_IN * F_HID * sizeof(float), 0, cudaMemcpyDeviceToDevice);
    cudaMemcpyToSymbolAsync(c_b1, b1, F_HID * sizeof(float), 0, cudaMemcpyDeviceToDevice);
    cudaMemcpyToSymbolAsync(c_W2, W2, F_HID * sizeof(float), 0, cudaMemcpyDeviceToDevice);

    const int TB = 256;
    const int gridN = (N_NODES + TB - 1) / TB;
    const int gridE = (N_EDGES + TB - 1) / TB;

    k_deg_acc<<<gridE, TB>>>(ei, w);
    k_dinv_xs<<<gridN, TB>>>(x);
    k_layer1_edges<<<gridE, TB>>>(ei, w);
    k_node_mlp<<<gridN, TB>>>(x);
    k_layer2_edges<<<gridE, TB>>>(ei, w);
    k_out<<<gridN, TB>>>(b2, out);
}

// round 15
// speedup vs baseline: 1.1121x; 1.0218x over previous
#include <cuda_runtime.h>
#include <cuda_fp16.h>
#include <cuda_bf16.h>

#define N_NODES 100000
#define N_EDGES 3200000
#define F_IN 8
#define F_HID 64
#define P_W1 0
#define P_B1 (F_IN * F_HID)          // 512
#define P_W2 (P_B1 + F_HID)          // 576
#define P_TOT (P_W2 + F_HID)         // 640

// Scratch: __device__ globals (GPU DRAM; allocation-free rule)
__device__ float g_deg[N_NODES];                           // accumulated WITHOUT self-loop
__device__ float g_dinv[N_NODES];
__device__ __align__(16) unsigned g_xsh[N_NODES * 4];      // dinv[i]*x[i] as 8 fp16 (4x half2)
__device__ __align__(16) unsigned g_acc1h[N_NODES * 4];    // 8 fp16 accumulators/node (4x half2)
__device__ float g_sd[N_NODES];                            // dinv[i] * s[i]
__device__ float g_acc2[N_NODES];                          // layer-2 accumulator
__device__ float g_stage[P_TOT];                           // param staging (contiguous)

// MLP params in constant memory (uniform LDC path; one D2D memcpy per call)
__constant__ float c_params[P_TOT];

__device__ __forceinline__ unsigned h2_bits(__half2 h) {
    union { __half2 h; unsigned u; } cvt; cvt.h = h; return cvt.u;
}
__device__ __forceinline__ __half2 bits_h2(unsigned u) {
    union { unsigned u; __half2 h; } cvt; cvt.u = u; return cvt.h;
}

// packed f32x2 helpers (Blackwell dual-issue FMA: FFMA2 only via PTX fma.rn.f32x2)
#define PACK_F32X2(out, lo, hi) \
    asm("mov.b64 %0, {%1, %2};" : "=l"(out) : "f"(lo), "f"(hi))
#define UNPACK_F32X2(lo, hi, in) \
    asm("mov.b64 {%0, %1}, %2;" : "=f"(lo), "=f"(hi) : "l"(in))
#define FMA_F32X2(d, a, b, c) \
    asm("fma.rn.f32x2 %0, %1, %2, %3;" : "=l"(d) : "l"(a), "l"(b), "l"(c))

// ---------------------------------------------------------------------------
// 0) prep: zero deg (self-loop handled in dinv) + pack W1|b1|W2 into g_stage
__global__ void k_prep(const float* __restrict__ W1, const float* __restrict__ b1,
                       const float* __restrict__ W2) {
    int i = blockIdx.x * blockDim.x + threadIdx.x;
    if (i < N_NODES) g_deg[i] = 0.0f;
    if (i < P_B1) g_stage[i] = W1[i];
    else if (i < P_W2) g_stage[i] = b1[i - P_B1];
    else if (i < P_TOT) g_stage[i] = W2[i - P_W2];
}

// 1) deg accumulate: deg[col] += w
__global__ void k_deg_acc(const int* __restrict__ ei, const float* __restrict__ w) {
    int e = blockIdx.x * blockDim.x + threadIdx.x;
    if (e >= N_EDGES) return;
    atomicAdd(&g_deg[ei[N_EDGES + e]], w[e]);
}

// 2) dinv = rsqrt(1 + deg); xsh = fp16(dinv*x); zero acc1h & acc2 (fused init)
__global__ void k_dinv_xs(const float* __restrict__ x) {
    int i = blockIdx.x * blockDim.x + threadIdx.x;
    if (i >= N_NODES) return;
    float dv = rsqrtf(1.0f + g_deg[i]);     // +1 = self-loop weight
    g_dinv[i] = dv;
    const float4* xr = (const float4*)(x + (size_t)i * F_IN);
    float4 a = xr[0], b = xr[1];
    uint4 pk;
    pk.x = h2_bits(__floats2half2_rn(a.x * dv, a.y * dv));
    pk.y = h2_bits(__floats2half2_rn(a.z * dv, a.w * dv));
    pk.z = h2_bits(__floats2half2_rn(b.x * dv, b.y * dv));
    pk.w = h2_bits(__floats2half2_rn(b.z * dv, b.w * dv));
    ((uint4*)g_xsh)[i] = pk;
    ((uint4*)g_acc1h)[i] = make_uint4(0u, 0u, 0u, 0u);
    g_acc2[i] = 0.0f;
}

// fire-and-forget packed-half reduction: 8 halves in one 16B RED (sm_103a)
__device__ __forceinline__ void red_add_v4_f16x2(unsigned* p, unsigned h0, unsigned h1,
                                                 unsigned h2, unsigned h3) {
    asm volatile("red.global.add.noftz.v4.f16x2 [%0], {%1,%2,%3,%4};"
                 :: "l"(p), "r"(h0), "r"(h1), "r"(h2), "r"(h3) : "memory");
}

// 3) layer-1 edge pass, 1 edge/thread: acc1[c] += w * xs[r]
//    1 LDG.128 gather (fp16 xs) + 1 RED.128; multiply in fp32 for precision.
__global__ void k_layer1_edges(const int* __restrict__ ei, const float* __restrict__ w) {
    int e = blockIdx.x * blockDim.x + threadIdx.x;
    if (e >= N_EDGES) return;
    int r = ei[e];
    int c = ei[N_EDGES + e];
    float we = w[e];
    uint4 u = __ldg((const uint4*)(g_xsh + (size_t)r * 4));
    float2 p0 = __half22float2(bits_h2(u.x));
    float2 p1 = __half22float2(bits_h2(u.y));
    float2 p2 = __half22float2(bits_h2(u.z));
    float2 p3 = __half22float2(bits_h2(u.w));
    unsigned h0 = h2_bits(__floats2half2_rn(we * p0.x, we * p0.y));
    unsigned h1 = h2_bits(__floats2half2_rn(we * p1.x, we * p1.y));
    unsigned h2 = h2_bits(__floats2half2_rn(we * p2.x, we * p2.y));
    unsigned h3 = h2_bits(__floats2half2_rn(we * p3.x, we * p3.y));
    red_add_v4_f16x2(g_acc1h + (size_t)c * 4, h0, h1, h2, h3);
}

// 4) node MLP, 1 thread/node, f-pairs via fma.rn.f32x2, params in __constant__:
//    a = dinv*acc1 + dinv^2*x ; s = relu(a@W1+b1)@W2 ; sd = dinv*s
__global__ void k_node_mlp(const float* __restrict__ x) {
    int i = blockIdx.x * blockDim.x + threadIdx.x;
    if (i >= N_NODES) return;

    float dv = g_dinv[i];
    float dv2 = dv * dv;
    uint4 u = __ldg((const uint4*)(g_acc1h + (size_t)i * 4));
    float2 f0 = __half22float2(bits_h2(u.x));
    float2 f1 = __half22float2(bits_h2(u.y));
    float2 f2 = __half22float2(bits_h2(u.z));
    float2 f3 = __half22float2(bits_h2(u.w));
    const float4* xr = (const float4*)(x + (size_t)i * F_IN);
    float4 X0 = __ldg(xr), X1 = __ldg(xr + 1);
    float a[F_IN];
    a[0] = dv * f0.x + dv2 * X0.x;  a[1] = dv * f0.y + dv2 * X0.y;
    a[2] = dv * f1.x + dv2 * X0.z;  a[3] = dv * f1.y + dv2 * X0.w;
    a[4] = dv * f2.x + dv2 * X1.x;  a[5] = dv * f2.y + dv2 * X1.y;
    a[6] = dv * f3.x + dv2 * X1.z;  a[7] = dv * f3.y + dv2 * X1.w;

    // broadcast-pack each a[k] into both halves once
    unsigned long long apk[F_IN];
    #pragma unroll
    for (int k = 0; k < F_IN; k++) PACK_F32X2(apk[k], a[k], a[k]);

    const unsigned long long* W1p = (const unsigned long long*)(c_params + P_W1); // [k][fp] pairs
    const float2* b1p = (const float2*)(c_params + P_B1);
    const float*  W2  = c_params + P_W2;

    float s = 0.0f;
    #pragma unroll
    for (int fp = 0; fp < F_HID / 2; fp++) {
        float2 bb = b1p[fp];
        unsigned long long acc;
        PACK_F32X2(acc, bb.x, bb.y);
        #pragma unroll
        for (int k = 0; k < F_IN; k++)
            FMA_F32X2(acc, apk[k], W1p[k * (F_HID / 2) + fp], acc);
        float lo, hi;
        UNPACK_F32X2(lo, hi, acc);
        s = fmaf(fmaxf(lo, 0.0f), W2[2 * fp],     s);
        s = fmaf(fmaxf(hi, 0.0f), W2[2 * fp + 1], s);
    }
    g_sd[i] = dv * s;
}

// 5) layer-2 edge pass, 1 edge/thread: acc2[c] += w * sd[r]
__global__ void k_layer2_edges(const int* __restrict__ ei, const float* __restrict__ w) {
    int e = blockIdx.x * blockDim.x + threadIdx.x;
    if (e >= N_EDGES) return;
    int r = ei[e];
    int c = ei[N_EDGES + e];
    atomicAdd(&g_acc2[c], w[e] * __ldg(&g_sd[r]));
}

// 6) epilogue, 4 nodes/thread: out = b2 + dinv * (acc2 + sd)
__global__ void k_out(const float* __restrict__ b2, float* __restrict__ out) {
    int t = blockIdx.x * blockDim.x + threadIdx.x;
    int i = t * 4;
    if (i >= N_NODES) return;
    float bb = b2[0];
    float4 dv = *(const float4*)(g_dinv + i);
    float4 a2 = *(const float4*)(g_acc2 + i);
    float4 sd = *(const float4*)(g_sd + i);
    float4 o;
    o.x = bb + dv.x * (a2.x + sd.x);
    o.y = bb + dv.y * (a2.y + sd.y);
    o.z = bb + dv.z * (a2.z + sd.z);
    o.w = bb + dv.w * (a2.w + sd.w);
    *(float4*)(out + i) = o;
}

extern "C" void kernel_launch(void* const* d_in, const int* in_sizes, int n_in,
                              void* d_out, int out_size) {
    const float* x  = (const float*)d_in[0];
    const int*   ei = (const int*)d_in[1];     // int32 (JAX x64 disabled)
    const float* w  = (const float*)d_in[2];
    const float* W1 = (const float*)d_in[3];
    const float* b1 = (const float*)d_in[4];
    const float* W2 = (const float*)d_in[5];
    const float* b2 = (const float*)d_in[6];
    float* out = (float*)d_out;

    const int TB = 256;
    const int gridN = (N_NODES + TB - 1) / TB;
    const int gridE = (N_EDGES + TB - 1) / TB;

    // 0) zero deg + pack params (one kernel), then ONE D2D copy into __constant__
    k_prep<<<gridN, TB>>>(W1, b1, W2);
    void* cparams_ptr = nullptr;
    void* stage_ptr = nullptr;
    cudaGetSymbolAddress(&cparams_ptr, c_params);
    cudaGetSymbolAddress(&stage_ptr, g_stage);
    cudaMemcpyAsync(cparams_ptr, stage_ptr, P_TOT * sizeof(float), cudaMemcpyDeviceToDevice);

    k_deg_acc<<<gridE, TB>>>(ei, w);
    k_dinv_xs<<<gridN, TB>>>(x);
    k_layer1_edges<<<gridE, TB>>>(ei, w);
    k_node_mlp<<<gridN, TB>>>(x);
    k_layer2_edges<<<gridE, TB>>>(ei, w);
    k_out<<<(N_NODES / 4 + TB - 1) / TB, TB>>>(b2, out);
}